// round 15
// baseline (speedup 1.0000x reference)
#include <cuda_runtime.h>
#include <cuda_fp16.h>
#include <cuda.h>
#include <math.h>
#include <stdint.h>

typedef __half BF;
typedef __half2 BF2;

// ---------------- constants ----------------
#define Bn   8
#define Dm_  512
#define FFNn 2048
#define Ln   8
#define OUTn 1024
#define Hn   8
#define DHn  64
#define QN   336
#define SN   320
#define RTn  64
#define Un   256
#define NSEG 16

// token space: 0..14 mems | 15..78 rc | 79..334 utt | 335..350 summary | 351 pad

// ------- float arena -------
#define F_X    0UL
#define F_S    (F_X + 1064960UL)
#define F_QKV  (F_S + 1310720UL)
#define F_H2A  (F_QKV + 4325376UL)
#define F_H2B  (F_H2A + 1310720UL)
#define F_H2C  (F_H2B + 1310720UL)
#define F_YB   (F_H2C + 1310720UL)
#define F_BQKV (F_YB + 2097152UL)
#define F_TOT  (F_BQKV + 12288UL)
__device__ __align__(1024) float g_arena[F_TOT];

// ------- fp16 arena ----
#define EQ    262144UL
#define EQKV  786432UL
#define EW1   1048576UL
#define EOUT  524288UL
#define EU    1441792UL
#define EAT   1376256UL
#define EHB   1310720UL
#define EFB   5242880UL
#define EYT   1048576UL

#define BW_QKV 0UL
#define BW_O   (BW_QKV + 8UL*2UL*EQKV)
#define BW_1   (BW_O   + 8UL*2UL*EQ)
#define BW_2   (BW_1   + 8UL*2UL*EW1)
#define BW_OUT (BW_2   + 8UL*2UL*EW1)
#define BA_U   (BW_OUT + 2UL*EOUT)
#define BA_AT  (BA_U   + 2UL*EU)
#define BA_HB  (BA_AT  + 2UL*EAT)
#define BA_FB  (BA_HB  + 2UL*EHB)
#define BA_YT  (BA_FB  + 2UL*EFB)
#define B_TOT  (BA_YT  + 2UL*EYT)
__device__ __align__(1024) BF g_bf[B_TOT];

// grid-barrier state (generation-based; survives graph replays)
__device__ int g_cnt[4];
__device__ volatile int g_gen[4];

__device__ __forceinline__ void grid_bar(int id, int n) {
    __syncthreads();
    if (threadIdx.x == 0) {
        __threadfence();
        int gen = g_gen[id];
        if (atomicAdd(&g_cnt[id], 1) == n - 1) {
            g_cnt[id] = 0;
            __threadfence();
            g_gen[id] = gen + 1;
        } else {
            while (g_gen[id] == gen) __nanosleep(64);
        }
        __threadfence();
    }
    __syncthreads();
}

__device__ __forceinline__ void split2(float x, BF& h, BF& l) {
    h = __float2half(x);
    l = __float2half(x - __half2float(h));
}
__device__ __forceinline__ BF2 mk2(BF a, BF b) { return __halves2half2(a, b); }

// ============ TMA / mbarrier primitives ============
__device__ __forceinline__ uint32_t smem_u32(const void* p) {
    return (uint32_t)__cvta_generic_to_shared(p);
}
__device__ __forceinline__ void mbar_init(uint32_t a, uint32_t cnt) {
    asm volatile("mbarrier.init.shared::cta.b64 [%0], %1;" :: "r"(a), "r"(cnt) : "memory");
}
__device__ __forceinline__ void mbar_expect(uint32_t a, uint32_t tx) {
    asm volatile("mbarrier.arrive.expect_tx.shared::cta.b64 _, [%0], %1;"
                 :: "r"(a), "r"(tx) : "memory");
}
__device__ __forceinline__ void mbar_arrive(uint32_t a) {
    asm volatile("mbarrier.arrive.shared::cta.b64 _, [%0];" :: "r"(a) : "memory");
}
__device__ __forceinline__ void mbar_wait(uint32_t a, uint32_t ph) {
    uint32_t done = 0;
    while (!done) {
        asm volatile(
            "{\n\t.reg .pred p;\n\t"
            "mbarrier.try_wait.parity.acquire.cta.shared::cta.b64 p, [%1], %2, 0x989680;\n\t"
            "selp.b32 %0, 1, 0, p;\n\t}"
            : "=r"(done) : "r"(a), "r"(ph) : "memory");
    }
}
__device__ __forceinline__ void tma3d(uint32_t dst, const void* map,
                                      int cx, int cy, int cz, uint32_t mbar) {
    asm volatile(
        "cp.async.bulk.tensor.3d.shared::cta.global.tile.mbarrier::complete_tx::bytes "
        "[%0], [%1, {%2, %3, %4}], [%5];"
        :: "r"(dst), "l"(map), "r"(cx), "r"(cy), "r"(cz), "r"(mbar) : "memory");
}
__device__ __forceinline__ void mma2(float c[4], const uint32_t a[4],
                                     uint32_t b0, uint32_t b1) {
    asm volatile(
        "mma.sync.aligned.m16n8k16.row.col.f32.f16.f16.f32 "
        "{%0,%1,%2,%3}, {%4,%5,%6,%7}, {%8,%9}, {%0,%1,%2,%3};\n"
        : "+f"(c[0]), "+f"(c[1]), "+f"(c[2]), "+f"(c[3])
        : "r"(a[0]), "r"(a[1]), "r"(a[2]), "r"(a[3]), "r"(b0), "r"(b1));
}
#define LDSM4(r, a) \
    asm volatile("ldmatrix.sync.aligned.m8n8.x4.shared.b16 {%0,%1,%2,%3}, [%4];" \
        : "=r"((r)[0]), "=r"((r)[1]), "=r"((r)[2]), "=r"((r)[3]) : "r"(a))

#define NST 3

// ============ GEMM mainloop core (SW64, 32-K stages, fp16) ============
template <int MT, int NT, int AP>
__device__ __forceinline__ void gemm_core(
    const CUtensorMap* tmA, const CUtensorMap* tmB, char* smx,
    int row0, int col0, int kstart, int K,
    float (&acc)[MT / 64][NT / 16][4])
{
    constexpr int MSPAN = MT / 4;
    constexpr int MTM   = MT / 64;
    constexpr int NSPAN = NT / 2;
    constexpr int NNT   = NT / 16;
    constexpr int APL   = MT * 64;
    constexpr int BPL   = NT * 64;
    constexpr int STB   = AP * APL + BPL;
    const uint32_t sb = smem_u32(smx);
    const uint32_t db = (sb + 1023) & ~1023u;
    const int tid = threadIdx.x, lane = tid & 31, wid = tid >> 5;
    const int wm = wid & 3, wn = wid >> 2;
    const int T = K >> 5;

    const uint32_t barb = db + NST * STB;
    if (tid == 0) {
        for (int s = 0; s < NST; s++) {
            mbar_init(barb + s * 8, 1);
            mbar_init(barb + 64 + s * 8, 256);
        }
    }
    __syncthreads();

    if (tid == 0) {
        for (int s = 0; s < NST; s++) {
            uint32_t st = db + s * STB, fb = barb + s * 8;
            mbar_expect(fb, STB);
            tma3d(st, tmA, kstart + s * 32, row0, 0, fb);
            if (AP == 2) tma3d(st + APL, tmA, kstart + s * 32, row0, 1, fb);
            tma3d(st + AP * APL, tmB, kstart + s * 32, col0, 0, fb);
        }
    }

    const int lrow = (lane & 7) + (((lane >> 3) & 1) << 3);
    const int kofs = ((lane >> 4) & 1) * 8;
    const uint32_t msk = (uint32_t)((lrow >> 1) & 3) << 4;
    uint32_t arow_off[MTM], brow_off[NNT / 2];
#pragma unroll
    for (int mt = 0; mt < MTM; mt++)
        arow_off[mt] = (uint32_t)(wm * MSPAN + mt * 16 + lrow) * 64;
#pragma unroll
    for (int p = 0; p < NNT / 2; p++)
        brow_off[p] = (uint32_t)(wn * NSPAN + p * 16 + lrow) * 64;

    uint32_t pfm = 0, pem = 0;
    for (int i = 0; i < T; i++) {
        const int bslot = i % NST;
        const uint32_t fb = barb + bslot * 8, eb = barb + 64 + bslot * 8;
        mbar_wait(fb, (pfm >> bslot) & 1); pfm ^= (1u << bslot);
        const uint32_t sA = db + bslot * STB, sB = sA + AP * APL;
#pragma unroll
        for (int kk = 0; kk < 32; kk += 16) {
            const uint32_t csw = ((uint32_t)((kk + kofs) * 2)) ^ msk;
            uint32_t ah[MTM][4], al_[MTM][4], bh[NNT / 2][4];
#pragma unroll
            for (int mt = 0; mt < MTM; mt++) {
                uint32_t ad = sA + arow_off[mt] + csw;
                LDSM4(ah[mt], ad);
                if (AP == 2) LDSM4(al_[mt], ad + APL);
            }
#pragma unroll
            for (int p = 0; p < NNT / 2; p++) {
                LDSM4(bh[p], sB + brow_off[p] + csw);
            }
#pragma unroll
            for (int nt = 0; nt < NNT; nt++) {
                const int p = nt >> 1, s1 = nt & 1;
#pragma unroll
                for (int mt = 0; mt < MTM; mt++) {
                    mma2(acc[mt][nt], ah[mt], bh[p][s1], bh[p][2 + s1]);
                    if (AP == 2)
                        mma2(acc[mt][nt], al_[mt], bh[p][s1], bh[p][2 + s1]);
                }
            }
        }
        mbar_arrive(eb);
        if (tid == 0 && i + NST < T) {
            mbar_wait(eb, (pem >> bslot) & 1); pem ^= (1u << bslot);
            uint32_t st = db + bslot * STB;
            mbar_expect(fb, STB);
            int k0 = kstart + (i + NST) * 32;
            tma3d(st, tmA, k0, row0, 0, fb);
            if (AP == 2) tma3d(st + APL, tmA, k0, row0, 1, fb);
            tma3d(st + AP * APL, tmB, k0, col0, 0, fb);
        }
    }
}

// ---- LN row helper (warp-collective, D=512, hi plane out) ----
__device__ __forceinline__ void ln_row_body(
    const float* X, const float* g, const float* bta, BF* oh, int row)
{
    const int lane = threadIdx.x & 31;
    const float4* x = (const float4*)(X + (long)row * 512);
    float s = 0.f, s2 = 0.f;
    float4 a0_[4];
#pragma unroll
    for (int i = 0; i < 4; i++) {
        float4 a = x[lane + i * 32];
        a0_[i] = a;
        s  += a.x + a.y + a.z + a.w;
        s2 += a.x * a.x + a.y * a.y + a.z * a.z + a.w * a.w;
    }
#pragma unroll
    for (int o = 16; o; o >>= 1) {
        s  += __shfl_xor_sync(~0u, s, o);
        s2 += __shfl_xor_sync(~0u, s2, o);
    }
    const float mean = s * (1.f / 512.f);
    const float inv = rsqrtf(s2 * (1.f / 512.f) - mean * mean + 1e-5f);
    const float4* gg = (const float4*)g;
    const float4* bb = (const float4*)bta;
#pragma unroll
    for (int i = 0; i < 4; i++) {
        int idx = lane + i * 32;
        float4 a = a0_[i], gv = gg[idx], bv = bb[idx];
        float o0 = (a.x - mean) * inv * gv.x + bv.x;
        float o1 = (a.y - mean) * inv * gv.y + bv.y;
        float o2 = (a.z - mean) * inv * gv.z + bv.z;
        float o3 = (a.w - mean) * inv * gv.w + bv.w;
        long base = (long)row * 512 + idx * 4;
        *(BF2*)&oh[base]     = mk2(__float2half(o0), __float2half(o1));
        *(BF2*)&oh[base + 2] = mk2(__float2half(o2), __float2half(o3));
    }
}

// ============ fused kernel: QKV GEMM + attention ============
__global__ __launch_bounds__(256, 2) void k_qkv(
    const __grid_constant__ CUtensorMap tmA,
    const __grid_constant__ CUtensorMap tmB,
    const float* __restrict__ bias, float* __restrict__ QKVf,
    const int* __restrict__ lengths, BF* __restrict__ Ah)
{
    extern __shared__ __align__(16) char smx[];
    float acc[2][8][4] = {};
    const int row0 = blockIdx.y * 128, col0 = blockIdx.x * 128;
    gemm_core<128, 128, 1>(&tmA, &tmB, smx, row0, col0, 0, 512, acc);

    const int tid = threadIdx.x, lane = tid & 31, wid = tid >> 5;
    const int wm = wid & 3, wn = wid >> 2;
    const int grp = lane >> 2, tig = lane & 3;
#pragma unroll
    for (int mt = 0; mt < 2; mt++) {
        const long r = row0 + wm * 32 + mt * 16 + grp;
#pragma unroll
        for (int nt = 0; nt < 8; nt++) {
            const long c = col0 + wn * 64 + nt * 8 + tig * 2;
            float b0 = bias[c], b1 = bias[c + 1];
            *(float2*)&QKVf[r * 1536 + c] =
                make_float2(acc[mt][nt][0] + b0, acc[mt][nt][1] + b1);
            *(float2*)&QKVf[(r + 8) * 1536 + c] =
                make_float2(acc[mt][nt][2] + b0, acc[mt][nt][3] + b1);
        }
    }

    grid_bar(0, 264);

    // ---- attention tail: grid-stride over 84*8 = 672 items ----
    const uint32_t db = (smem_u32(smx) + 1023) & ~1023u;
    float (*sc)[64] = (float(*)[64])smx;          // reuse stage smem (dead)
    short (*ki)[64] = (short(*)[64])(smx + 2048 + (db - smem_u32(smx)));
    const int h = wid;
    int maxlr = 0;
#pragma unroll
    for (int i = 0; i < Bn; i++) maxlr = max(maxlr, lengths[i] >> 2);
    const int linear = blockIdx.y * 12 + blockIdx.x;
    const int g = lane >> 3, e = lane & 7;

    for (int item = linear; item < 672; item += 264) {
        const int qb = item / 84, q4 = item % 84;
        const int lrb = lengths[qb] >> 2;
        const float* Kb = QKVf + (size_t)qb * 1536 + 512 + h * DHn;
        const float* Vb = Kb + 512;
        for (int qq = 0; qq < 4; qq++) {
            const int qi = q4 * 4 + qq;
            int seg; bool summ = false;
            if (qi < RTn)      seg = qi >> 2;
            else if (qi < SN)  seg = (qi - RTn) >> 4;
            else             { seg = qi - SN; summ = true; }
            const int ms  = max(seg - 4, 0);
            const int ss  = max(seg * 16 - 32, 0);
            const int se  = min(seg * 16 + 16, Un);
            const int ue  = min(se, lrb + 256 - maxlr);
            const int rcs = 15 + seg * 4;
            const int c0 = summ ? 0 : (seg - ms);
            const int c2 = max(ue - ss, 0);
            const int n  = c0 + 4 + c2;

            for (int j = lane; j < n; j += 32) {
                int k;
                if (j < c0)          k = ms + j;
                else if (j < c0 + 4) k = rcs + (j - c0);
                else                 k = 79 + ss + (j - c0 - 4);
                ki[h][j] = (short)k;
            }
            __syncwarp();

            const float4* qv = (const float4*)(QKVf + ((size_t)(15 + qi) * Bn + qb) * 1536 + h * DHn);
            float4 q0 = qv[e * 2], q1 = qv[e * 2 + 1];
            q0.x *= 0.125f; q0.y *= 0.125f; q0.z *= 0.125f; q0.w *= 0.125f;
            q1.x *= 0.125f; q1.y *= 0.125f; q1.z *= 0.125f; q1.w *= 0.125f;

            for (int j0 = 0; j0 < n; j0 += 4) {
                int j = j0 + g;
                float p = 0.f;
                if (j < n) {
                    const float4* kp = (const float4*)(Kb + (size_t)ki[h][j] * (Bn * 1536));
                    float4 k0 = kp[e * 2], k1 = kp[e * 2 + 1];
                    p = q0.x * k0.x + q0.y * k0.y + q0.z * k0.z + q0.w * k0.w
                      + q1.x * k1.x + q1.y * k1.y + q1.z * k1.z + q1.w * k1.w;
                }
                p += __shfl_xor_sync(~0u, p, 4);
                p += __shfl_xor_sync(~0u, p, 2);
                p += __shfl_xor_sync(~0u, p, 1);
                if (e == 0 && j < n) sc[h][j] = p;
            }
            __syncwarp();

            float m = -3.4e38f;
            for (int j = lane; j < n; j += 32) m = fmaxf(m, sc[h][j]);
#pragma unroll
            for (int o = 16; o; o >>= 1) m = fmaxf(m, __shfl_xor_sync(~0u, m, o));
            float sum = 0.f;
            for (int j = lane; j < n; j += 32) {
                float e2 = expf(sc[h][j] - m);
                sc[h][j] = e2;
                sum += e2;
            }
#pragma unroll
            for (int o = 16; o; o >>= 1) sum += __shfl_xor_sync(~0u, sum, o);
            __syncwarp();
            const float inv = 1.f / sum;

            float a0 = 0.f, a1 = 0.f;
            for (int j = 0; j < n; j++) {
                float p = sc[h][j];
                const float2 vp = *(const float2*)(Vb + (size_t)ki[h][j] * (Bn * 1536) + 2 * lane);
                a0 = fmaf(p, vp.x, a0);
                a1 = fmaf(p, vp.y, a1);
            }
            a0 *= inv; a1 *= inv;
            size_t op = ((size_t)qi * Bn + qb) * Dm_ + h * DHn + 2 * lane;
            *(BF2*)&Ah[op] = mk2(__float2half(a0), __float2half(a1));
            __syncwarp();
        }
    }
}

// ============ fused kernel: O-proj GEMM (+residual, tanh-mems) + LN_ff ======
__global__ __launch_bounds__(256, 2) void k_oproj(
    const __grid_constant__ CUtensorMap tmA,
    const __grid_constant__ CUtensorMap tmB,
    const float* __restrict__ bias, float* __restrict__ S,
    BF* __restrict__ Uh, const float* __restrict__ ffg,
    const float* __restrict__ ffb, BF* __restrict__ HBh)
{
    extern __shared__ __align__(16) char smx[];
    float acc[1][8][4] = {};
    const int row0 = blockIdx.y * 64, col0 = blockIdx.x * 128;
    gemm_core<64, 128, 1>(&tmA, &tmB, smx, row0, col0, 0, 512, acc);

    const int tid = threadIdx.x, lane = tid & 31, wid = tid >> 5;
    const int wm = wid & 3, wn = wid >> 2;
    const int grp = lane >> 2, tig = lane & 3;
    {
        const long r = row0 + wm * 16 + grp;
#pragma unroll
        for (int nt = 0; nt < 8; nt++) {
            const long c = col0 + wn * 64 + nt * 8 + tig * 2;
            float b0 = bias[c], b1 = bias[c + 1];
            float v0 = acc[0][nt][0] + b0, v1 = acc[0][nt][1] + b1;
            float v2 = acc[0][nt][2] + b0, v3 = acc[0][nt][3] + b1;
#pragma unroll
            for (int rr = 0; rr < 2; rr++) {
                long r2 = r + rr * 8;
                float u0 = rr ? v2 : v0, u1 = rr ? v3 : v1;
                if (r2 < 2560) {
                    float2 s = *(float2*)&S[r2 * 512 + c];
                    *(float2*)&S[r2 * 512 + c] = make_float2(s.x + u0, s.y + u1);
                } else if (r2 < 2680) {
                    float t0 = tanhf(u0), t1 = tanhf(u1);
                    long o = (r2 - 2560) * 512 + c;
                    *(BF2*)&Uh[o] = mk2(__float2half(t0), __float2half(t1));
                }
            }
        }
    }

    grid_bar(1, 168);

    // ---- LN_ff tail: 1344 warps grid-stride 2560 rows (S -> HBh) ----
    const int linear = blockIdx.y * 4 + blockIdx.x;
    for (int row = linear * 8 + wid; row < 2560; row += 1344)
        ln_row_body(S, ffg, ffb, HBh, row);
}

// ===== fused kernel: FFN2 split-K GEMM + ln2(+next-layer LN1) + summary =====
__global__ __launch_bounds__(256, 2) void k_ffn2(
    const __grid_constant__ CUtensorMap tmA,
    const __grid_constant__ CUtensorMap tmB,
    const float* __restrict__ bias, float* __restrict__ H2A,
    float* __restrict__ S,
    const float* __restrict__ g1, const float* __restrict__ be1,
    const float* __restrict__ g2, const float* __restrict__ be2,
    BF* __restrict__ Uh)
{
    extern __shared__ __align__(16) char smx[];
    float acc[2][8][4] = {};
    const int row0 = blockIdx.y * 128, col0 = blockIdx.x * 128;
    const int kstart = blockIdx.z * 704;
    gemm_core<128, 128, 1>(&tmA, &tmB, smx, row0, col0, kstart, 704, acc);

    float* Cf = H2A + (long)blockIdx.z * 1310720;
    const float* bi = (blockIdx.z == 0) ? bias : nullptr;
    const int tid = threadIdx.x, lane = tid & 31, wid = tid >> 5;
    const int wm = wid & 3, wn = wid >> 2;
    const int grp = lane >> 2, tig = lane & 3;
#pragma unroll
    for (int mt = 0; mt < 2; mt++) {
        const long r = row0 + wm * 32 + mt * 16 + grp;
#pragma unroll
        for (int nt = 0; nt < 8; nt++) {
            const long c = col0 + wn * 64 + nt * 8 + tig * 2;
            float b0 = bi ? bi[c] : 0.f, b1 = bi ? bi[c + 1] : 0.f;
            *(float2*)&Cf[r * 512 + c] =
                make_float2(acc[mt][nt][0] + b0, acc[mt][nt][1] + b1);
            *(float2*)&Cf[(r + 8) * 512 + c] =
                make_float2(acc[mt][nt][2] + b0, acc[mt][nt][3] + b1);
        }
    }

    grid_bar(2, 240);

    // ---- ln2 tail: 1920 warps grid-stride 2560 rows ----
    const int linear = blockIdx.z * 80 + blockIdx.y * 4 + blockIdx.x;
    const float* HA = H2A;
    const float* HB_ = H2A + 1310720;
    const float* HC = H2A + 2621440;
    for (int row = linear * 8 + wid; row < 2560; row += 1920) {
        const float4* xs = (const float4*)(S   + (long)row * 512);
        const float4* xa = (const float4*)(HA  + (long)row * 512);
        const float4* xb = (const float4*)(HB_ + (long)row * 512);
        const float4* xc = (const float4*)(HC  + (long)row * 512);
        float4 R[4];
        float s = 0.f, s2 = 0.f;
#pragma unroll
        for (int i = 0; i < 4; i++) {
            int idx = lane + i * 32;
            float4 a = xs[idx], c = xa[idx], d = xb[idx], e = xc[idx];
            a.x += c.x + d.x + e.x; a.y += c.y + d.y + e.y;
            a.z += c.z + d.z + e.z; a.w += c.w + d.w + e.w;
            R[i] = a;
            s  += a.x + a.y + a.z + a.w;
            s2 += a.x * a.x + a.y * a.y + a.z * a.z + a.w * a.w;
        }
#pragma unroll
        for (int o = 16; o; o >>= 1) {
            s  += __shfl_xor_sync(~0u, s, o);
            s2 += __shfl_xor_sync(~0u, s2, o);
        }
        float mean = s * (1.f / 512.f);
        float inv = rsqrtf(s2 * (1.f / 512.f) - mean * mean + 1e-5f);
        const float4* g1v = (const float4*)g1; const float4* b1v = (const float4*)be1;
        float t = 0.f, t2 = 0.f;
#pragma unroll
        for (int i = 0; i < 4; i++) {
            int idx = lane + i * 32;
            float4 gv = g1v[idx], bv = b1v[idx], y;
            y.x = (R[i].x - mean) * inv * gv.x + bv.x;
            y.y = (R[i].y - mean) * inv * gv.y + bv.y;
            y.z = (R[i].z - mean) * inv * gv.z + bv.z;
            y.w = (R[i].w - mean) * inv * gv.w + bv.w;
            R[i] = y;
            ((float4*)(S + (long)row * 512))[idx] = y;
            t  += y.x + y.y + y.z + y.w;
            t2 += y.x * y.x + y.y * y.y + y.z * y.z + y.w * y.w;
        }
        if (g2) {
#pragma unroll
            for (int o = 16; o; o >>= 1) {
                t  += __shfl_xor_sync(~0u, t, o);
                t2 += __shfl_xor_sync(~0u, t2, o);
            }
            float mean2 = t * (1.f / 512.f);
            float inv2 = rsqrtf(t2 * (1.f / 512.f) - mean2 * mean2 + 1e-5f);
            const float4* g2v = (const float4*)g2; const float4* b2v = (const float4*)be2;
#pragma unroll
            for (int i = 0; i < 4; i++) {
                int idx = lane + i * 32;
                float4 gv = g2v[idx], bv = b2v[idx];
                float z0 = (R[i].x - mean2) * inv2 * gv.x + bv.x;
                float z1 = (R[i].y - mean2) * inv2 * gv.y + bv.y;
                float z2 = (R[i].z - mean2) * inv2 * gv.z + bv.z;
                float z3 = (R[i].w - mean2) * inv2 * gv.w + bv.w;
                long base = (long)(row + 120) * 512 + idx * 4;
                *(BF2*)&Uh[base]     = mk2(__float2half(z0), __float2half(z1));
                *(BF2*)&Uh[base + 2] = mk2(__float2half(z2), __float2half(z3));
            }
        }
    }

    if (!g2) return;
    grid_bar(3, 240);

    // ---- summary tail: 65536 elements grid-stride ----
    for (int idx = linear * 256 + tid; idx < 16 * 8 * 512; idx += 240 * 256) {
        int s = idx >> 12, rem = idx & 4095;
        int b = rem >> 9, d = rem & 511;
        size_t base = ((size_t)((79 + s * 16) * Bn) + b) * Dm_ + d;
        float acc2 = 0.f;
#pragma unroll
        for (int k = 0; k < 16; k++)
            acc2 += __half2float(Uh[base + (size_t)k * Bn * Dm_]);
        acc2 *= (1.f / 16.f);
        Uh[((size_t)((335 + s) * Bn) + b) * Dm_ + d] = __float2half(acc2);
    }
}

// ============ generic GEMM kernel (FFN1, out-proj) ============
template <int MT, int NT, int AP>
__global__ __launch_bounds__(256, 2) void gemm6(
    const __grid_constant__ CUtensorMap tmA,
    const __grid_constant__ CUtensorMap tmB,
    const float* __restrict__ bias, float* __restrict__ Cf,
    BF* __restrict__ Ch, int N, int K, int act)
{
    extern __shared__ __align__(16) char smx[];
    float acc[MT / 64][NT / 16][4] = {};
    const int row0 = blockIdx.y * MT, col0 = blockIdx.x * NT;
    gemm_core<MT, NT, AP>(&tmA, &tmB, smx, row0, col0, 0, K, acc);

    const int tid = threadIdx.x, lane = tid & 31, wid = tid >> 5;
    const int wm = wid & 3, wn = wid >> 2;
    const int grp = lane >> 2, tig = lane & 3;
#pragma unroll
    for (int mt = 0; mt < MT / 64; mt++) {
        const long r = row0 + wm * (MT / 4) + mt * 16 + grp;
#pragma unroll
        for (int nt = 0; nt < NT / 16; nt++) {
            const long c = col0 + wn * (NT / 2) + nt * 8 + tig * 2;
            float b0 = bias ? bias[c] : 0.f, b1 = bias ? bias[c + 1] : 0.f;
            float v0 = acc[mt][nt][0] + b0, v1 = acc[mt][nt][1] + b1;
            float v2 = acc[mt][nt][2] + b0, v3 = acc[mt][nt][3] + b1;
            if (act) {
                v0 = fmaxf(v0, 0.f); v1 = fmaxf(v1, 0.f);
                v2 = fmaxf(v2, 0.f); v3 = fmaxf(v3, 0.f);
            }
            if (Cf) {
                *(float2*)&Cf[r * N + c]       = make_float2(v0, v1);
                *(float2*)&Cf[(r + 8) * N + c] = make_float2(v2, v3);
            }
            if (Ch) {
                *(BF2*)&Ch[r * N + c]       = mk2(__float2half(v0), __float2half(v1));
                *(BF2*)&Ch[(r + 8) * N + c] = mk2(__float2half(v2), __float2half(v3));
            }
        }
    }
}

// ---------------- legacy in-kernel-convert GEMM (input proj, K=80) ---------
#define LLDA 40
__global__ __launch_bounds__(256) void gemm_tc(
    const float* __restrict__ A, const float* __restrict__ W,
    float* __restrict__ C, int M, int N, int K)
{
    __shared__ BF Ahs[128 * LLDA], Als[128 * LLDA];
    __shared__ BF Bhs[128 * LLDA];
    const int tid = threadIdx.x, lane = tid & 31, wid = tid >> 5;
    const int wm = wid & 3, wn = wid >> 2;
    const int grp = lane >> 2, tig = lane & 3;
    const long row0 = (long)blockIdx.y * 128;
    const int  col0 = blockIdx.x * 128;
    float acc[2][8][4] = {};
    const int arow = tid >> 1, acol0 = (tid & 1) * 16;
    const int brow = tid >> 3, bcol0 = (tid & 7) * 16;

    for (int k0 = 0; k0 < K; k0 += 32) {
#pragma unroll
        for (int j = 0; j < 4; j++) {
            int c = acol0 + j * 4;
            float4 v = make_float4(0.f, 0.f, 0.f, 0.f);
            if (row0 + arow < M && k0 + c < K)
                v = *(const float4*)&A[(row0 + arow) * (long)K + k0 + c];
            BF h, l; int o = arow * LLDA + c;
            split2(v.x, h, l); Ahs[o]     = h; Als[o]     = l;
            split2(v.y, h, l); Ahs[o + 1] = h; Als[o + 1] = l;
            split2(v.z, h, l); Ahs[o + 2] = h; Als[o + 2] = l;
            split2(v.w, h, l); Ahs[o + 3] = h; Als[o + 3] = l;
        }
#pragma unroll
        for (int j = 0; j < 4; j++) {
            int n = bcol0 + j * 4;
            float4 v = make_float4(0.f, 0.f, 0.f, 0.f);
            if (k0 + brow < K)
                v = *(const float4*)&W[(long)(k0 + brow) * N + col0 + n];
            Bhs[(n + 0) * LLDA + brow] = __float2half(v.x);
            Bhs[(n + 1) * LLDA + brow] = __float2half(v.y);
            Bhs[(n + 2) * LLDA + brow] = __float2half(v.z);
            Bhs[(n + 3) * LLDA + brow] = __float2half(v.w);
        }
        __syncthreads();
#pragma unroll
        for (int kk = 0; kk < 32; kk += 16) {
            uint32_t ah[2][4], al[2][4];
#pragma unroll
            for (int mt = 0; mt < 2; mt++) {
                int r = wm * 32 + mt * 16;
                int o  = (r + grp) * LLDA + kk + tig * 2;
                int o8 = o + 8 * LLDA;
                ah[mt][0] = *(const uint32_t*)&Ahs[o];
                ah[mt][1] = *(const uint32_t*)&Ahs[o8];
                ah[mt][2] = *(const uint32_t*)&Ahs[o + 8];
                ah[mt][3] = *(const uint32_t*)&Ahs[o8 + 8];
                al[mt][0] = *(const uint32_t*)&Als[o];
                al[mt][1] = *(const uint32_t*)&Als[o8];
                al[mt][2] = *(const uint32_t*)&Als[o + 8];
                al[mt][3] = *(const uint32_t*)&Als[o8 + 8];
            }
#pragma unroll
            for (int nt = 0; nt < 8; nt++) {
                int nn = wn * 64 + nt * 8 + grp;
                int o = nn * LLDA + kk + tig * 2;
                uint32_t b0 = *(const uint32_t*)&Bhs[o], b1 = *(const uint32_t*)&Bhs[o + 8];
#pragma unroll
                for (int mt = 0; mt < 2; mt++) {
                    mma2(acc[mt][nt], ah[mt], b0, b1);
                    mma2(acc[mt][nt], al[mt], b0, b1);
                }
            }
        }
        __syncthreads();
    }
#pragma unroll
    for (int mt = 0; mt < 2; mt++) {
#pragma unroll
        for (int nt = 0; nt < 8; nt++) {
            int c = col0 + wn * 64 + nt * 8 + tig * 2;
            long r = row0 + wm * 32 + mt * 16 + grp;
            if (r < M)
                *(float2*)&C[r * N + c] = make_float2(acc[mt][nt][0], acc[mt][nt][1]);
            if (r + 8 < M)
                *(float2*)&C[(r + 8) * N + c] = make_float2(acc[mt][nt][2], acc[mt][nt][3]);
        }
    }
}

// ------- weight transpose+convert: out[n][k] = fp16(W[k][n]) ----
__global__ __launch_bounds__(256) void wconv_k(
    const float* __restrict__ W, BF* __restrict__ oh,
    int K, int N, long inS, long outS)
{
    __shared__ float t[32][129];
    const float* w = W + (long)blockIdx.z * inS;
    BF* ph = oh + (long)blockIdx.z * outS;
    const int n0 = blockIdx.x * 128, k0 = blockIdx.y * 32;
    const int r = threadIdx.x >> 5;
    const int c = threadIdx.x & 31;
#pragma unroll
    for (int i = 0; i < 4; i++) {
        int row = r + i * 8;
        float4 v = *(const float4*)&w[(long)(k0 + row) * N + n0 + c * 4];
        t[row][c * 4 + 0] = v.x; t[row][c * 4 + 1] = v.y;
        t[row][c * 4 + 2] = v.z; t[row][c * 4 + 3] = v.w;
    }
    __syncthreads();
    const int n = threadIdx.x >> 1, kc = (threadIdx.x & 1) * 16;
    __align__(16) BF h[16];
#pragma unroll
    for (int j = 0; j < 16; j++) h[j] = __float2half(t[kc + j][n]);
    long o = (long)(n0 + n) * K + k0 + kc;
    *(uint4*)&ph[o]     = *(uint4*)&h[0];
    *(uint4*)&ph[o + 8] = *(uint4*)&h[8];
}

// merged bias pack + UIN pad (hi plane only)
__global__ void prep_k(const float* __restrict__ bq, const float* __restrict__ bk,
                       const float* __restrict__ bv, float* __restrict__ o,
                       BF* __restrict__ uh)
{
    int i = blockIdx.x * blockDim.x + threadIdx.x;
    if (i < 12288) {
        int l = i / 1536, j = i % 1536;
        float v;
        if (j < 512)       v = bq[l * 512 + j];
        else if (j < 1024) v = bk[l * 512 + j - 512];
        else               v = bv[l * 512 + j - 1024];
        o[i] = v;
    }
    if (i < 4096) {
        size_t p = 2808UL * 512UL + i;
        uh[p] = __float2half(0.f);
    }
}

// ---------------- LayerNorm standalone (warp per row) ----------------
__global__ __launch_bounds__(256) void ln_row_k(
    const float* __restrict__ X, const float* __restrict__ g, const float* __restrict__ bta,
    float* __restrict__ outf, BF* __restrict__ oh, int D)
{
    const int wid = threadIdx.x >> 5, lane = threadIdx.x & 31;
    const int row = blockIdx.x * 8 + wid;
    const float4* x = (const float4*)(X + (long)row * D);
    const int cnt = D >> 7;
    float s = 0.f, s2 = 0.f;
    for (int i = 0; i < cnt; i++) {
        float4 a = x[lane + i * 32];
        s  += a.x + a.y + a.z + a.w;
        s2 += a.x * a.x + a.y * a.y + a.z * a.z + a.w * a.w;
    }
#pragma unroll
    for (int o = 16; o; o >>= 1) {
        s  += __shfl_xor_sync(~0u, s, o);
        s2 += __shfl_xor_sync(~0u, s2, o);
    }
    const float mean = s / D;
    const float inv = rsqrtf(s2 / D - mean * mean + 1e-5f);
    const float4* gg = (const float4*)g;
    const float4* bb = (const float4*)bta;
    for (int i = 0; i < cnt; i++) {
        int idx = lane + i * 32;
        float4 a = x[idx], gv = gg[idx], bv = bb[idx], o;
        o.x = (a.x - mean) * inv * gv.x + bv.x;
        o.y = (a.y - mean) * inv * gv.y + bv.y;
        o.z = (a.z - mean) * inv * gv.z + bv.z;
        o.w = (a.w - mean) * inv * gv.w + bv.w;
        if (outf) ((float4*)(outf + (long)row * D))[idx] = o;
        if (oh) {
            long base = (long)row * D + idx * 4;
            *(BF2*)&oh[base]     = mk2(__float2half(o.x), __float2half(o.y));
            *(BF2*)&oh[base + 2] = mk2(__float2half(o.z), __float2half(o.w));
        }
    }
}

// ---------------- misc ----------------
__global__ void initS_k(const float* __restrict__ X, float* __restrict__ S)
{
    const int t = blockIdx.x, b = blockIdx.y, d = threadIdx.x;
    int frame;
    if (t < RTn) {
        int si = t >> 2;
        int st = (si == 15) ? 256 : (si + 1) * 16;
        frame = st + (t & 3);
    } else frame = t - RTn;
    S[((size_t)t * Bn + b) * Dm_ + d] = X[(size_t)b * 133120 + (size_t)frame * Dm_ + d];
}

__global__ void mems0_k(const float* __restrict__ S, BF* __restrict__ uh)
{
    const int s = blockIdx.x, b = blockIdx.y, d = threadIdx.x;
    size_t base = ((size_t)(RTn + s * 16) * Bn + b) * Dm_ + d;
    float acc = 0.f;
#pragma unroll
    for (int k = 0; k < 16; k++) acc += S[base + (size_t)k * Bn * Dm_];
    acc *= (1.f / 16.f);
    uh[((size_t)s * Bn + b) * Dm_ + d] = __float2half(acc);
}

__global__ void summary_pl_k(BF* __restrict__ uh)
{
    const int s = blockIdx.x, b = blockIdx.y, d = threadIdx.x;
    size_t base = ((size_t)((79 + s * 16) * Bn) + b) * Dm_ + d;
    float acc = 0.f;
#pragma unroll
    for (int k = 0; k < 16; k++)
        acc += __half2float(uh[base + (size_t)k * Bn * Dm_]);
    acc *= (1.f / 16.f);
    uh[((size_t)((335 + s) * Bn) + b) * Dm_ + d] = __float2half(acc);
}

// transpose + hi/lo split for out-proj (2-pass A)
__global__ void transpose_pl_k(const float* __restrict__ S, BF* __restrict__ yh,
                               BF* __restrict__ yl)
{
    const int r = blockIdx.x, d = threadIdx.x;
    const int b = r >> 8, u = r & 255;
    float v = S[((size_t)(RTn + u) * Bn + b) * Dm_ + d];
    BF h, l; split2(v, h, l);
    yh[(size_t)r * Dm_ + d] = h;
    yl[(size_t)r * Dm_ + d] = l;
}

__global__ void lr_k(const int* __restrict__ lengths, float* __restrict__ out)
{
    int i = threadIdx.x;
    if (i < Bn) out[i] = (float)(lengths[i] >> 2);
}

// ---------------- host: tensormap plumbing ----------------
typedef CUresult (*EncFn)(CUtensorMap*, CUtensorMapDataType, cuuint32_t, void*,
                          const cuuint64_t*, const cuuint64_t*, const cuuint32_t*,
                          const cuuint32_t*, CUtensorMapInterleave, CUtensorMapSwizzle,
                          CUtensorMapL2promotion, CUtensorMapFloatOOBfill);

static EncFn get_enc() {
    void* p = nullptr;
    cudaDriverEntryPointQueryResult qr;
#if CUDART_VERSION >= 12050
    if (cudaGetDriverEntryPointByVersion("cuTensorMapEncodeTiled", &p, 12000,
                                         cudaEnableDefault, &qr) == cudaSuccess && p)
        return (EncFn)p;
    p = nullptr;
#endif
    cudaGetDriverEntryPoint("cuTensorMapEncodeTiled", &p, cudaEnableDefault, &qr);
    return (EncFn)p;
}

static CUtensorMap mkmap(EncFn enc, const BF* base, long K, long M, long planeStride,
                         unsigned boxM) {
    CUtensorMap m;
    cuuint64_t dims[3]    = {(cuuint64_t)K, (cuuint64_t)M, 2};
    cuuint64_t strides[2] = {(cuuint64_t)K * 2, (cuuint64_t)planeStride * 2};
    cuuint32_t box[3]     = {32, boxM, 1};
    cuuint32_t es[3]      = {1, 1, 1};
    enc(&m, CU_TENSOR_MAP_DATA_TYPE_FLOAT16, 3, (void*)base, dims, strides, box, es,
        CU_TENSOR_MAP_INTERLEAVE_NONE, CU_TENSOR_MAP_SWIZZLE_64B,
        CU_TENSOR_MAP_L2_PROMOTION_L2_128B, CU_TENSOR_MAP_FLOAT_OOB_FILL_NONE);
    return m;
}

// ---------------- launch ----------------
extern "C" void kernel_launch(void* const* d_in, const int* in_sizes, int n_in,
                              void* d_out, int out_size)
{
    const float* input   = (const float*)d_in[0];
    const int*   lengths = (const int*)  d_in[1];
    const float* w_in    = (const float*)d_in[2];
    const float* ln_in_g = (const float*)d_in[3];
    const float* ln_in_b = (const float*)d_in[4];
    const float* wq = (const float*)d_in[5];
    const float* bq = (const float*)d_in[6];
    const float* wk = (const float*)d_in[7];
    const float* bk = (const float*)d_in[8];
    const float* wv = (const float*)d_in[9];
    const float* bv = (const float*)d_in[10];
    const float* wo = (const float*)d_in[11];
    const float* bo = (const float*)d_in[12];
    const float* ff_g = (const float*)d_in[13];
    const float* ff_b = (const float*)d_in[14];
    const float* w1 = (const float*)d_in[15];
    const float* b1 = (const float*)d_in[16];
    const float* w2 = (const float*)d_in[17];
    const float* b2 = (const float*)d_in[18];
    const float* lo_g = (const float*)d_in[19];
    const float* lo_b = (const float*)d_in[20];
    const float* w_out = (const float*)d_in[21];
    const float* b_out = (const float*)d_in[22];
    const float* lng = (const float*)d_in[23];
    const float* lnb = (const float*)d_in[24];
    float* out = (float*)d_out;

    float* fa = nullptr; BF* bf = nullptr;
    cudaGetSymbolAddress((void**)&fa, g_arena);
    cudaGetSymbolAddress((void**)&bf, g_bf);

    const int SM_QKV   = 1024 + NST * (8192 + 8192) + 128;       // 50304
    const int SM_O     = 1024 + NST * (4096 + 8192) + 128;       // 38016
    const int SM_FFN1  = 1024 + NST * (8192 + 4096) + 128;       // 38016
    const int SM_FFN2  = 1024 + NST * (8192 + 8192) + 128;       // 50304
    const int SM_OUT   = 1024 + NST * (2 * 4096 + 8192) + 128;   // 50304
    cudaFuncSetAttribute(k_qkv,  cudaFuncAttributeMaxDynamicSharedMemorySize, SM_QKV);
    cudaFuncSetAttribute(k_oproj, cudaFuncAttributeMaxDynamicSharedMemorySize, SM_O);
    cudaFuncSetAttribute(k_ffn2, cudaFuncAttributeMaxDynamicSharedMemorySize, SM_FFN2);
    cudaFuncSetAttribute(gemm6<128,64,1>, cudaFuncAttributeMaxDynamicSharedMemorySize, SM_FFN1);
    cudaFuncSetAttribute(gemm6<64,128,2>, cudaFuncAttributeMaxDynamicSharedMemorySize, SM_OUT);

    float* X    = fa + F_X;
    float* S    = fa + F_S;
    float* QKVf = fa + F_QKV;
    float* H2A  = fa + F_H2A;
    float* Yb   = fa + F_YB;
    float* BQKV = fa + F_BQKV;

    BF* UINh = bf + BA_U;
    BF* ATTh = bf + BA_AT;
    BF* HBh  = bf + BA_HB;
    BF* FBh  = bf + BA_FB;
    BF* YTh  = bf + BA_YT;  BF* YTl = YTh + EYT;

    EncFn enc = get_enc();
    CUtensorMap mUIN = mkmap(enc, UINh, 512, 2816, EU, 128);
    CUtensorMap mATT = mkmap(enc, ATTh, 512, 2688, EAT, 64);
    CUtensorMap mHB  = mkmap(enc, HBh,  512, 2560, EHB, 128);
    CUtensorMap mFB  = mkmap(enc, FBh, 2048, 2560, EFB, 128);
    CUtensorMap mYT  = mkmap(enc, YTh,  512, 2048, EYT, 64);
    CUtensorMap mOUT = mkmap(enc, bf + BW_OUT, 512, 1024, EOUT, 128);
    CUtensorMap mWQKV[Ln], mWO[Ln], mW1[Ln], mW2[Ln];
    for (int l = 0; l < Ln; l++) {
        mWQKV[l] = mkmap(enc, bf + BW_QKV + (size_t)l * 2 * EQKV, 512, 1536, EQKV, 128);
        mWO[l]   = mkmap(enc, bf + BW_O   + (size_t)l * 2 * EQ,   512,  512, EQ, 128);
        mW1[l]   = mkmap(enc, bf + BW_1   + (size_t)l * 2 * EW1,  512, 2048, EW1, 64);
        mW2[l]   = mkmap(enc, bf + BW_2   + (size_t)l * 2 * EW1, 2048,  512, EW1, 128);
    }

    // ---- per-replay preprocessing ----
    gemm_tc<<<dim3(1, 65), 256>>>(input, w_in, X, 8320, 128, 80);
    initS_k<<<dim3(SN, Bn), Dm_>>>(X, S);
    mems0_k<<<dim3(15, Bn), Dm_>>>(S, UINh);

    wconv_k<<<dim3(4, 16, 8), 256>>>(wq, bf + BW_QKV, 512, 512, EQ, 2 * EQKV);
    wconv_k<<<dim3(4, 16, 8), 256>>>(wk, bf + BW_QKV + 262144, 512, 512, EQ, 2 * EQKV);
    wconv_k<<<dim3(4, 16, 8), 256>>>(wv, bf + BW_QKV + 524288, 512, 512, EQ, 2 * EQKV);
    wconv_k<<<dim3(4, 16, 8), 256>>>(wo, bf + BW_O, 512, 512, EQ, 2 * EQ);
    wconv_k<<<dim3(16, 16, 8), 256>>>(w1, bf + BW_1, 512, 2048, EW1, 2 * EW1);
    wconv_k<<<dim3(4, 64, 8), 256>>>(w2, bf + BW_2, 2048, 512, EW1, 2 * EW1);
    wconv_k<<<dim3(8, 16, 1), 256>>>(w_out, bf + BW_OUT, 512, 1024, 0, 0);
    prep_k<<<48, 256>>>(bq, bk, bv, BQKV, UINh);

    // layer-0 LN1 + summary
    ln_row_k<<<SN * Bn / 8, 256>>>(S, ln_in_g, ln_in_b, nullptr,
                                   UINh + 120 * 512, Dm_);
    summary_pl_k<<<dim3(NSEG, Bn), Dm_>>>(UINh);

    for (int l = 0; l < Ln; l++) {
        k_qkv<<<dim3(12, 22, 1), 256, SM_QKV>>>(mUIN, mWQKV[l], BQKV + l * 1536,
                                                QKVf, lengths, ATTh);

        k_oproj<<<dim3(4, 42, 1), 256, SM_O>>>(mATT, mWO[l], bo + l * Dm_,
                                               S, UINh, ff_g + l * Dm_,
                                               ff_b + l * Dm_, HBh);

        gemm6<128,64,1><<<dim3(32, 20, 1), 256, SM_FFN1>>>(
            mHB, mW1[l], b1 + l * FFNn, nullptr, FBh, 2048, 512, 1);

        const float* g2 = (l + 1 < Ln) ? (ln_in_g + (l + 1) * Dm_) : nullptr;
        const float* b2n = (l + 1 < Ln) ? (ln_in_b + (l + 1) * Dm_) : nullptr;
        k_ffn2<<<dim3(4, 20, 3), 256, SM_FFN2>>>(mFB, mW2[l], b2 + l * Dm_,
                                                 H2A, S,
                                                 lo_g + l * Dm_, lo_b + l * Dm_,
                                                 g2, b2n, UINh);
    }

    transpose_pl_k<<<2048, Dm_>>>(S, YTh, YTl);
    gemm6<64,128,2><<<dim3(8, 32, 1), 256, SM_OUT>>>(
        mYT, mOUT, b_out, Yb, nullptr, 1024, 512, 0);
    ln_row_k<<<2048 / 8, 256>>>(Yb, lng, lnb, out, nullptr, OUTn);

    if (out_size >= 2048 * 1024 + Bn)
        lr_k<<<1, 32>>>(lengths, out + 2048 * 1024);
}